// round 9
// baseline (speedup 1.0000x reference)
#include <cuda_runtime.h>
#include <cuda_fp16.h>
#include <math.h>

#define N_NODES 50000
#define N_EDGES 800000
#define IN_CH   64
#define HID     128

// ---------------- scratch (static device globals; no allocation) ----------------
__device__ int   g_cnt[N_NODES];
__device__ int   g_off[N_NODES];
__device__ int   g_cur[N_NODES];
__device__ int   g_bsum[256];
__device__ int   g_csr[N_EDGES];                        // src node id per CSR slot (keyed by dst)
__device__ __align__(16) float  g_h[N_NODES * HID];     // hidden activations (fp32, self term)
__device__ __align__(16) __half g_hh[N_NODES * HID];    // hidden activations (fp16, gather copy)
__device__ __align__(16) __half g_xh[N_NODES * IN_CH];  // x in fp16 (gather copy)
__device__ __align__(16) float  g_mean[N_NODES * HID];  // mean-aggregated neighbor features
__device__ __align__(16) float  g_W0[(2 * IN_CH) * HID];// [K][128] k-major (tf32-rounded)
__device__ __align__(16) float  g_W1[(2 * HID) * HID];
__device__ __align__(16) float  g_W2[(2 * HID) * HID];

// ---------------- tf32 helpers ----------------
__device__ __forceinline__ float to_tf32(float x) {
    unsigned u;
    asm("cvt.rna.tf32.f32 %0, %1;" : "=r"(u) : "f"(x));
    return __uint_as_float(u);
}
__device__ __forceinline__ void mma_tf32(float* d, unsigned a0, unsigned a1,
                                         unsigned a2, unsigned a3,
                                         unsigned b0, unsigned b1) {
    asm volatile(
        "mma.sync.aligned.m16n8k8.row.col.f32.tf32.tf32.f32 "
        "{%0,%1,%2,%3}, {%4,%5,%6,%7}, {%8,%9}, {%0,%1,%2,%3};"
        : "+f"(d[0]), "+f"(d[1]), "+f"(d[2]), "+f"(d[3])
        : "r"(a0), "r"(a1), "r"(a2), "r"(a3), "r"(b0), "r"(b1));
}

// ---------------- CSR build (R4-proven path) ----------------
__global__ void k_zero_cnt() {
    int i = blockIdx.x * blockDim.x + threadIdx.x;
    if (i < N_NODES) g_cnt[i] = 0;
}

// edge_index is int32 on the wire (JAX x64 disabled downgrades int64 -> int32).
__global__ void k_count(const int* __restrict__ ei) {
    int e = blockIdx.x * blockDim.x + threadIdx.x;
    if (e < N_EDGES) {
        int dst = ei[N_EDGES + e];
        if ((unsigned)dst < (unsigned)N_NODES)
            atomicAdd(&g_cnt[dst], 1);
    }
}

__global__ void k_scan1() {
    __shared__ int s[256];
    int i = blockIdx.x * 256 + threadIdx.x;
    int v = (i < N_NODES) ? g_cnt[i] : 0;
    s[threadIdx.x] = v;
    __syncthreads();
    for (int off = 1; off < 256; off <<= 1) {
        int t = (threadIdx.x >= off) ? s[threadIdx.x - off] : 0;
        __syncthreads();
        s[threadIdx.x] += t;
        __syncthreads();
    }
    if (i < N_NODES) g_off[i] = s[threadIdx.x] - v;
    if (threadIdx.x == 255) g_bsum[blockIdx.x] = s[255];
}

__global__ void k_scan2(int nb) {
    __shared__ int s[256];
    int v = (threadIdx.x < nb) ? g_bsum[threadIdx.x] : 0;
    s[threadIdx.x] = v;
    __syncthreads();
    for (int off = 1; off < 256; off <<= 1) {
        int t = (threadIdx.x >= off) ? s[threadIdx.x - off] : 0;
        __syncthreads();
        s[threadIdx.x] += t;
        __syncthreads();
    }
    g_bsum[threadIdx.x] = s[threadIdx.x] - v;
}

__global__ void k_scan3() {
    int i = blockIdx.x * blockDim.x + threadIdx.x;
    if (i < N_NODES) {
        int o = g_off[i] + g_bsum[i >> 8];
        g_off[i] = o;
        g_cur[i] = o;
    }
}

__global__ void k_fill(const int* __restrict__ ei) {
    int e = blockIdx.x * blockDim.x + threadIdx.x;
    if (e < N_EDGES) {
        int src = ei[e];
        int dst = ei[N_EDGES + e];
        if ((unsigned)dst < (unsigned)N_NODES && (unsigned)src < (unsigned)N_NODES) {
            int pos = atomicAdd(&g_cur[dst], 1);
            if ((unsigned)pos < (unsigned)N_EDGES) g_csr[pos] = src;
        }
    }
}

// ---------------- weight transpose+concat: Wcat[k][f], tf32-rounded ----------------
__global__ void k_wcat(const float* __restrict__ Wl, const float* __restrict__ Wr,
                       int DIN, int layer) {
    float* dst = (layer == 0) ? g_W0 : (layer == 1) ? g_W1 : g_W2;
    int i = blockIdx.x * blockDim.x + threadIdx.x;
    int total = 2 * DIN * HID;
    if (i < total) {
        int k = i >> 7;
        int f = i & 127;
        float v = (k < DIN) ? Wl[f * DIN + k] : Wr[f * DIN + (k - DIN)];
        dst[i] = to_tf32(v);
    }
}

// ---------------- x -> fp16 copy ----------------
__global__ void k_x2h(const float* __restrict__ x) {
    int i = blockIdx.x * blockDim.x + threadIdx.x;
    if (i < N_NODES * IN_CH / 2) {
        float2 v = ((const float2*)x)[i];
        ((half2*)g_xh)[i] = __floats2half2_rn(v.x, v.y);
    }
}

// ---------------- aggregation d=64 (fp16 src): two nodes per warp ----------------
__global__ void k_agg64h() {
    int w    = (blockIdx.x * blockDim.x + threadIdx.x) >> 5;
    int lane = threadIdx.x & 31;
    int node = w * 2 + (lane >> 4);
    int il   = lane & 15;
    if (node >= N_NODES) return;
    int start = g_off[node];
    int cnt   = g_cnt[node];
    const uint2* __restrict__ x2 = (const uint2*)g_xh;
    float ax = 0.f, ay = 0.f, az = 0.f, aw = 0.f;
    for (int e = 0; e < cnt; e++) {
        int s = g_csr[start + e];
        uint2 v = x2[(size_t)s * 16 + il];
        float2 lo = __half22float2(*(const half2*)&v.x);
        float2 hi = __half22float2(*(const half2*)&v.y);
        ax += lo.x; ay += lo.y; az += hi.x; aw += hi.y;
    }
    float inv = 1.f / fmaxf((float)cnt, 1.f);
    ((float4*)g_mean)[(size_t)node * 16 + il] =
        make_float4(ax * inv, ay * inv, az * inv, aw * inv);
}

// ---------------- aggregation d=128 (fp16 src): warp per node ----------------
__global__ void k_agg128h() {
    int gw   = (blockIdx.x * blockDim.x + threadIdx.x) >> 5;
    int lane = threadIdx.x & 31;
    if (gw >= N_NODES) return;
    int start = g_off[gw];
    int cnt   = g_cnt[gw];
    const uint2* __restrict__ h2 = (const uint2*)g_hh;
    float ax = 0.f, ay = 0.f, az = 0.f, aw = 0.f;
    for (int e = 0; e < cnt; e++) {
        int s = g_csr[start + e];
        uint2 v = h2[(size_t)s * 32 + lane];
        float2 lo = __half22float2(*(const half2*)&v.x);
        float2 hi = __half22float2(*(const half2*)&v.y);
        ax += lo.x; ay += lo.y; az += hi.x; aw += hi.y;
    }
    float inv = 1.f / fmaxf((float)cnt, 1.f);
    ((float4*)g_mean)[(size_t)gw * 32 + lane] =
        make_float4(ax * inv, ay * inv, az * inv, aw * inv);
}

// ---------------- fused TF32 mma transform + L2-normalize (+relu) ----------------
// out = normalize(mean@Wl^T + bias + x@Wr^T), K = 2*DIN virtual reduction.
// Block: 256 threads (8 warps), tile 128 nodes x 128 f.
// Warp: 16 nodes x 128 f via 16 m16n8k8 tf32 mma tiles per 8-k step.
// As[node][kk] stride 36: frag-load bank = 4g+t (conflict-free), STS conflict-free.
// Ws[kk][f]   stride 132: frag-load bank = 4t+g (conflict-free).
#define AS_S 36
#define WS_S 132
__global__ __launch_bounds__(256) void k_transform(
    const float* __restrict__ xin, int use_h, int layer,
    const float* __restrict__ bias, int DIN, int relu, int to_out,
    float* __restrict__ dout)
{
    const float* __restrict__ A1 = g_mean;
    const float* __restrict__ A2 = use_h ? g_h : xin;
    const float* __restrict__ W  = (layer == 0) ? g_W0 : (layer == 1) ? g_W1 : g_W2;

    __shared__ __align__(16) float As[128 * AS_S];   // 18432 B
    __shared__ __align__(16) float Ws[32 * WS_S];    // 16896 B

    const int tid   = threadIdx.x;
    const int warp  = tid >> 5;
    const int lane  = tid & 31;
    const int g     = lane >> 2;          // 0..7 (mma group)
    const int t     = lane & 3;           // 0..3 (thread in group)
    const int m0    = warp * 16;          // warp's node offset in tile
    const int node0 = blockIdx.x * 128;

    // accumulators: 16 n-tiles x 4 regs, bias folded in (same bias both rows)
    float acc[16][4];
#pragma unroll
    for (int nt = 0; nt < 16; nt++) {
        float b0 = bias[nt * 8 + 2 * t];
        float b1 = bias[nt * 8 + 2 * t + 1];
        acc[nt][0] = b0; acc[nt][1] = b1; acc[nt][2] = b0; acc[nt][3] = b1;
    }

    const int K   = 2 * DIN;
    const int lkk = tid & 31;             // A loader: k within chunk
    const int lng = tid >> 5;             // A loader: node group (16 nodes)
    const int lf  = tid & 127;            // W loader: f
    const int lkg = tid >> 7;             // W loader: k group (16 kk)

    for (int c0 = 0; c0 < K; c0 += 32) {
        const float* Asrc = (c0 < DIN) ? A1 : A2;
        const int cb = (c0 < DIN) ? c0 : (c0 - DIN);
#pragma unroll
        for (int r = 0; r < 16; r++) {
            int n = lng * 16 + r;
            int node = node0 + n;
            float v = (node < N_NODES) ? Asrc[(size_t)node * DIN + cb + lkk] : 0.f;
            As[n * AS_S + lkk] = to_tf32(v);
        }
#pragma unroll
        for (int r = 0; r < 16; r++) {
            int kk = lkg * 16 + r;
            Ws[kk * WS_S + lf] = W[(size_t)(c0 + kk) * 128 + lf];
        }
        __syncthreads();

#pragma unroll
        for (int ks = 0; ks < 4; ks++) {
            const int kb = ks * 8;
            unsigned a0 = __float_as_uint(As[(m0 + g)     * AS_S + kb + t]);
            unsigned a1 = __float_as_uint(As[(m0 + g + 8) * AS_S + kb + t]);
            unsigned a2 = __float_as_uint(As[(m0 + g)     * AS_S + kb + t + 4]);
            unsigned a3 = __float_as_uint(As[(m0 + g + 8) * AS_S + kb + t + 4]);
#pragma unroll
            for (int nt = 0; nt < 16; nt++) {
                unsigned b0 = __float_as_uint(Ws[(kb + t)     * WS_S + nt * 8 + g]);
                unsigned b1 = __float_as_uint(Ws[(kb + t + 4) * WS_S + nt * 8 + g]);
                mma_tf32(acc[nt], a0, a1, a2, a3, b0, b1);
            }
        }
        __syncthreads();
    }

    // ---- epilogue: per-row sum of squares, quad reduce, normalize, store ----
    float ss0 = 0.f, ss1 = 0.f;           // rows m0+g and m0+g+8
#pragma unroll
    for (int nt = 0; nt < 16; nt++) {
        ss0 += acc[nt][0] * acc[nt][0] + acc[nt][1] * acc[nt][1];
        ss1 += acc[nt][2] * acc[nt][2] + acc[nt][3] * acc[nt][3];
    }
    ss0 += __shfl_xor_sync(0xffffffffu, ss0, 1);
    ss0 += __shfl_xor_sync(0xffffffffu, ss0, 2);
    ss1 += __shfl_xor_sync(0xffffffffu, ss1, 1);
    ss1 += __shfl_xor_sync(0xffffffffu, ss1, 2);
    float sc0 = 1.f / fmaxf(sqrtf(ss0), 1e-12f);
    float sc1 = 1.f / fmaxf(sqrtf(ss1), 1e-12f);

    const int r0 = node0 + m0 + g;
    const int r1 = r0 + 8;
    float* __restrict__ dest = to_out ? dout : g_h;
#pragma unroll
    for (int nt = 0; nt < 16; nt++) {
        int col = nt * 8 + 2 * t;
        if (r0 < N_NODES) {
            float v0 = acc[nt][0] * sc0, v1 = acc[nt][1] * sc0;
            if (relu) { v0 = fmaxf(v0, 0.f); v1 = fmaxf(v1, 0.f); }
            *(float2*)&dest[(size_t)r0 * 128 + col] = make_float2(v0, v1);
            if (!to_out)
                *(half2*)&g_hh[(size_t)r0 * 128 + col] = __floats2half2_rn(v0, v1);
        }
        if (r1 < N_NODES) {
            float v0 = acc[nt][2] * sc1, v1 = acc[nt][3] * sc1;
            if (relu) { v0 = fmaxf(v0, 0.f); v1 = fmaxf(v1, 0.f); }
            *(float2*)&dest[(size_t)r1 * 128 + col] = make_float2(v0, v1);
            if (!to_out)
                *(half2*)&g_hh[(size_t)r1 * 128 + col] = __floats2half2_rn(v0, v1);
        }
    }
}

// ---------------- launch ----------------
extern "C" void kernel_launch(void* const* d_in, const int* in_sizes, int n_in,
                              void* d_out, int out_size) {
    const float* x   = (const float*)d_in[0];
    const int*   ei  = (const int*)d_in[1];     // int32 (JAX x64-disabled)
    const float* Wl0 = (const float*)d_in[2];
    const float* bl0 = (const float*)d_in[3];
    const float* Wr0 = (const float*)d_in[4];
    const float* Wl1 = (const float*)d_in[5];
    const float* bl1 = (const float*)d_in[6];
    const float* Wr1 = (const float*)d_in[7];
    const float* Wl2 = (const float*)d_in[8];
    const float* bl2 = (const float*)d_in[9];
    const float* Wr2 = (const float*)d_in[10];
    float* out = (float*)d_out;

    const int NB_NODE   = (N_NODES + 255) / 256;
    const int NB_EDGE   = (N_EDGES + 255) / 256;
    const int NB_AGG128 = (N_NODES + 7) / 8;
    const int NB_AGG64  = (N_NODES / 2 + 7) / 8;
    const int NB_TRANS  = (N_NODES + 127) / 128;
    const int NB_X2H    = (N_NODES * IN_CH / 2 + 255) / 256;

    // CSR build
    k_zero_cnt<<<NB_NODE, 256>>>();
    k_count<<<NB_EDGE, 256>>>(ei);
    k_scan1<<<NB_NODE, 256>>>();
    k_scan2<<<1, 256>>>(NB_NODE);
    k_scan3<<<NB_NODE, 256>>>();
    k_fill<<<NB_EDGE, 256>>>(ei);

    // weight prep (tf32-rounded) + x fp16 copy
    k_wcat<<<(2 * IN_CH * HID + 255) / 256, 256>>>(Wl0, Wr0, IN_CH, 0);
    k_wcat<<<(2 * HID * HID + 255) / 256, 256>>>(Wl1, Wr1, HID, 1);
    k_wcat<<<(2 * HID * HID + 255) / 256, 256>>>(Wl2, Wr2, HID, 2);
    k_x2h<<<NB_X2H, 256>>>(x);

    // layer 0: x (d=64) -> g_h/g_hh (relu)
    k_agg64h<<<NB_AGG64, 256>>>();
    k_transform<<<NB_TRANS, 256>>>(x, 0, 0, bl0, IN_CH, 1, 0, out);

    // layer 1: g_hh (d=128) -> g_h/g_hh (relu)
    k_agg128h<<<NB_AGG128, 256>>>();
    k_transform<<<NB_TRANS, 256>>>(x, 1, 1, bl1, HID, 1, 0, out);

    // layer 2: g_hh (d=128) -> out (no relu)
    k_agg128h<<<NB_AGG128, 256>>>();
    k_transform<<<NB_TRANS, 256>>>(x, 1, 2, bl2, HID, 0, 1, out);
}